// round 5
// baseline (speedup 1.0000x reference)
#include <cuda_runtime.h>
#include <cuda_fp16.h>
#include <math.h>

#define HIDDEN 256
#define NPTS   4096
#define KANCH  64
#define ND     400             // d-table rows: x in [0, 50), h = 1/8
#define NA     112             // a-table rows: x in [0, 14), h = 1/8
#define RPB    8               // rows per build block
#define INV_H  8.0f            // table rows per unit x

// -ln(10000)/256
#define NEG_LOG1E4_OVER_256 (-0.0359778921f)
// FACTOR_A = 180/(15*pi)
#define FACTOR_A 3.8197186342f

__device__ float g_WdT[HIDDEN * HIDDEN];
__device__ float g_WaT[HIDDEN * HIDDEN];
// Per row r, per channel quad t (t=0..63), channels 4t..4t+3:
//   .x = half2(v[4t],  v[4t+1])   .y = half2(dv[4t], dv[4t+1])
//   .z = half2(v[4t+2],v[4t+3])   .w = half2(dv[4t+2],dv[4t+3])
__device__ uint4 g_pd[ND * (HIDDEN / 4)];
__device__ uint4 g_pa[NA * (HIDDEN / 4)];

__device__ __forceinline__ __half2 as_h2(unsigned int v) {
    __half2 h;
    *reinterpret_cast<unsigned int*>(&h) = v;
    return h;
}
__device__ __forceinline__ unsigned int as_u32(__half2 h) {
    return *reinterpret_cast<unsigned int*>(&h);
}

// ---------------------------------------------------------------------------
// Transpose Wd, Wa (o-major -> h-major). grid (8,8,2), block (32,8)
// ---------------------------------------------------------------------------
__global__ void transpose_kernel(const float* __restrict__ Wd,
                                 const float* __restrict__ Wa) {
    __shared__ float tile[32][33];
    const float* src = blockIdx.z ? Wa : Wd;
    float*       dst = blockIdx.z ? g_WaT : g_WdT;
    int x = blockIdx.x * 32 + threadIdx.x;
    int y = blockIdx.y * 32 + threadIdx.y;
#pragma unroll
    for (int dy = 0; dy < 32; dy += 8)
        tile[threadIdx.y + dy][threadIdx.x] = src[(y + dy) * HIDDEN + x];
    __syncthreads();
    int xo = blockIdx.y * 32 + threadIdx.x;
    int yo = blockIdx.x * 32 + threadIdx.y;
#pragma unroll
    for (int dy = 0; dy < 32; dy += 8)
        dst[(yo + dy) * HIDDEN + xo] = tile[threadIdx.x][threadIdx.y + dy];
}

// ---------------------------------------------------------------------------
// Build half2-packed lookup tables. One block computes RPB rows (+1 overlap
// row for the delta). grid (ND+NA)/RPB = 64 blocks, 256 threads.
// ---------------------------------------------------------------------------
__global__ void build_kernel(const float* __restrict__ bd,
                             const float* __restrict__ ba) {
    __shared__ float emb[RPB + 1][HIDDEN];
    __shared__ float accs[RPB + 1][HIDDEN];
    const int b   = blockIdx.x;
    const int tid = threadIdx.x;
    const bool is_a = (b >= ND / RPB);
    const int row0  = is_a ? (b - ND / RPB) * RPB : b * RPB;
    const float* WT   = is_a ? g_WaT : g_WdT;
    const float* bias = is_a ? ba : bd;
    uint4* out        = is_a ? g_pa : g_pd;

    for (int e = tid; e < (RPB + 1) * 128; e += blockDim.x) {
        int rr = e >> 7;
        int i  = e & 127;
        float x = (float)(row0 + rr) * (1.0f / INV_H);
        float w = expf((float)(2 * i) * NEG_LOG1E4_OVER_256);
        float s, c;
        sincosf(x * w, &s, &c);
        emb[rr][2 * i]     = s;
        emb[rr][2 * i + 1] = c;
    }
    __syncthreads();

    const int o = tid;
    float acc[RPB + 1];
#pragma unroll
    for (int rr = 0; rr <= RPB; rr++) acc[rr] = 0.0f;
    for (int h = 0; h < HIDDEN; h++) {
        float w = __ldg(&WT[h * HIDDEN + o]);
#pragma unroll
        for (int rr = 0; rr <= RPB; rr++)
            acc[rr] = fmaf(emb[rr][h], w, acc[rr]);
    }
    float bo = __ldg(&bias[o]);
#pragma unroll
    for (int rr = 0; rr <= RPB; rr++) accs[rr][o] = acc[rr] + bo;
    __syncthreads();

    // pack channel quads into (v01, dv01, v23, dv23)
    if (tid < 64) {
        const int t = tid;
#pragma unroll
        for (int rr = 0; rr < RPB; rr++) {
            float a0 = accs[rr][4 * t],     a1 = accs[rr][4 * t + 1];
            float a2 = accs[rr][4 * t + 2], a3 = accs[rr][4 * t + 3];
            float b0 = accs[rr + 1][4 * t],     b1 = accs[rr + 1][4 * t + 1];
            float b2 = accs[rr + 1][4 * t + 2], b3 = accs[rr + 1][4 * t + 3];
            uint4 pk;
            pk.x = as_u32(__floats2half2_rn(a0, a1));
            pk.y = as_u32(__floats2half2_rn(b0 - a0, b1 - a1));
            pk.z = as_u32(__floats2half2_rn(a2, a3));
            pk.w = as_u32(__floats2half2_rn(b2 - a2, b3 - a3));
            out[(row0 + rr) * 64 + t] = pk;
        }
    }
}

// ---------------------------------------------------------------------------
// Main pass: 2 points per 128-thread block; thread (p = tid>>6, t = tid&63)
// handles channels 4t..4t+3 of point n0+p via half2 vector lerp + max.
// ---------------------------------------------------------------------------
__global__ void __launch_bounds__(128)
main_kernel(const float* __restrict__ points,
            const float* __restrict__ anchors,
            float* __restrict__ out) {
    __shared__ uint2 s_idx[2][KANCH];   // {jd*64, ja*64}
    __shared__ uint2 s_f[2][KANCH];     // {fd half2-bcast, fa half2-bcast}

    const int n0  = blockIdx.x * 2;
    const int tid = threadIdx.x;
    const int p   = tid >> 6;
    const int t   = tid & 63;

    {   // geometry: one (point, k) per thread
        const int n = n0 + p;
        const int k = t;
        const float px = __ldg(&points[n * 3 + 0]);
        const float py = __ldg(&points[n * 3 + 1]);
        const float pz = __ldg(&points[n * 3 + 2]);
        const int k1 = (k + 1) & (KANCH - 1);
        const float ax = __ldg(&anchors[k * 3 + 0]);
        const float ay = __ldg(&anchors[k * 3 + 1]);
        const float az = __ldg(&anchors[k * 3 + 2]);
        const float bx = __ldg(&anchors[k1 * 3 + 0]);
        const float by = __ldg(&anchors[k1 * 3 + 1]);
        const float bz = __ldg(&anchors[k1 * 3 + 2]);

        float rx = px - ax, ry = py - ay, rz = pz - az;
        float ex = px - bx, ey = py - by, ez = pz - bz;

        // d index: dist/SIGMA_D * 8 rows/unit -> *40
        float dist = sqrtf(rx * rx + ry * ry + rz * rz);
        float td = fminf(dist * (INV_H / 0.2f), (float)ND - 1.01f);
        int   jd = (int)td;
        float fd = td - (float)jd;

        float cx = ry * ez - rz * ey;
        float cy = rz * ex - rx * ez;
        float cz = rx * ey - ry * ex;
        float sv = sqrtf(cx * cx + cy * cy + cz * cz);
        float cv = rx * ex + ry * ey + rz * ez;
        float ang = atan2f(sv, cv);
        float ta = fminf(ang * (FACTOR_A * INV_H), (float)NA - 1.01f);
        ta = fmaxf(ta, 0.0f);
        int   ja = (int)ta;
        float fa = ta - (float)ja;

        s_idx[p][k] = make_uint2((unsigned)(jd * 64), (unsigned)(ja * 64));
        s_f[p][k]   = make_uint2(as_u32(__float2half2_rn(fd)),
                                 as_u32(__float2half2_rn(fa)));
    }
    __syncthreads();

    __half2 accd0 = __float2half2_rn(-60000.0f), accd1 = accd0;
    __half2 acca0 = accd0,                       acca1 = accd0;

#pragma unroll 8
    for (int k = 0; k < KANCH; k++) {
        uint2 idx = s_idx[p][k];
        uint2 f   = s_f[p][k];
        uint4 vd  = __ldg(&g_pd[idx.x + t]);
        uint4 va  = __ldg(&g_pa[idx.y + t]);
        __half2 fdh = as_h2(f.x), fah = as_h2(f.y);
        accd0 = __hmax2(accd0, __hfma2(fdh, as_h2(vd.y), as_h2(vd.x)));
        accd1 = __hmax2(accd1, __hfma2(fdh, as_h2(vd.w), as_h2(vd.z)));
        acca0 = __hmax2(acca0, __hfma2(fah, as_h2(va.y), as_h2(va.x)));
        acca1 = __hmax2(acca1, __hfma2(fah, as_h2(va.w), as_h2(va.z)));
    }

    float4 r;
    r.x = __low2float(accd0)  + __low2float(acca0);
    r.y = __high2float(accd0) + __high2float(acca0);
    r.z = __low2float(accd1)  + __low2float(acca1);
    r.w = __high2float(accd1) + __high2float(acca1);
    reinterpret_cast<float4*>(out)[(n0 + p) * 64 + t] = r;
}

// ---------------------------------------------------------------------------
extern "C" void kernel_launch(void* const* d_in, const int* in_sizes, int n_in,
                              void* d_out, int out_size) {
    const float* points  = (const float*)d_in[0];
    const float* anchors = (const float*)d_in[1];
    // d_in[2] = cor_score (unused by reference output)
    const float* Wa = (const float*)d_in[3];
    const float* ba = (const float*)d_in[4];
    const float* Wd = (const float*)d_in[5];
    const float* bd = (const float*)d_in[6];
    float* out = (float*)d_out;

    transpose_kernel<<<dim3(8, 8, 2), dim3(32, 8)>>>(Wd, Wa);
    build_kernel<<<(ND + NA) / RPB, HIDDEN>>>(bd, ba);
    main_kernel<<<NPTS / 2, 128>>>(points, anchors, out);
}